// round 2
// baseline (speedup 1.0000x reference)
#include <cuda_runtime.h>
#include <cstdint>

// Problem constants
namespace {
constexpr int Bb = 16384, Ss = 5, Dd = 512, Hh = 8, HDd = 64;
constexpr int Mm = Bb * Ss;  // 81920 rows
constexpr int BM = 128, BN = 128, BK = 32;
constexpr int SA_PAD = 36;   // As[BM][36]  (4g+t bank pattern -> conflict-free frag loads)
constexpr int SB_PAD = 136;  // Bs[BK][136] (8t+g bank pattern -> conflict-free frag loads)
}

// Scratch (device-global: allocation-free rule)
__device__ float g_Q[(size_t)Mm * Dd];
__device__ float g_K[(size_t)Mm * Dd];
__device__ float g_V[(size_t)Mm * Dd];
__device__ float g_O[(size_t)Mm * Dd];

__device__ __forceinline__ float to_tf32(float x) {
  float y;
  asm("cvt.rna.tf32.f32 %0, %1;" : "=f"(y) : "f"(x));
  return y;
}

__device__ __forceinline__ void mma_tf32(float c[4], uint32_t a0, uint32_t a1,
                                         uint32_t a2, uint32_t a3,
                                         uint32_t b0, uint32_t b1) {
  asm volatile(
      "mma.sync.aligned.m16n8k8.row.col.f32.tf32.tf32.f32 "
      "{%0,%1,%2,%3}, {%4,%5,%6,%7}, {%8,%9}, {%0,%1,%2,%3};"
      : "+f"(c[0]), "+f"(c[1]), "+f"(c[2]), "+f"(c[3])
      : "r"(a0), "r"(a1), "r"(a2), "r"(a3), "r"(b0), "r"(b1));
}

// C[M,Ntot] = A[M,512] @ W_sec[512,512] + bias_sec, sections of 512 cols pick (W0,W1,W2)
__global__ __launch_bounds__(256) void gemm_tf32_kernel(
    const float* __restrict__ A,
    const float* __restrict__ W0, const float* __restrict__ W1, const float* __restrict__ W2,
    const float* __restrict__ bias0, const float* __restrict__ bias1, const float* __restrict__ bias2,
    float* __restrict__ O0, float* __restrict__ O1, float* __restrict__ O2) {
  __shared__ float As[BM][SA_PAD];
  __shared__ float Bs[BK][SB_PAD];

  const int tid = threadIdx.x;
  const int m0 = blockIdx.y * BM;
  const int bx = blockIdx.x;
  const int sec = (bx * BN) >> 9;   // which 512-wide section
  const int n0 = (bx * BN) & 511;   // col offset inside section
  const float* W = (sec == 0) ? W0 : ((sec == 1) ? W1 : W2);
  const float* bias = (sec == 0) ? bias0 : ((sec == 1) ? bias1 : bias2);
  float* Out = (sec == 0) ? O0 : ((sec == 1) ? O1 : O2);

  const int warp = tid >> 5, lane = tid & 31;
  const int g = lane >> 2, t = lane & 3;
  const int warp_m = (warp >> 2) * 64;  // warps 2(m) x 4(n)
  const int warp_n = (warp & 3) * 32;

  float acc[4][4][4];
#pragma unroll
  for (int i = 0; i < 4; i++)
#pragma unroll
    for (int j = 0; j < 4; j++)
#pragma unroll
      for (int r = 0; r < 4; r++) acc[i][j][r] = 0.f;

  const int ar = tid >> 3;         // 0..31 (A row group)
  const int ac = (tid & 7) << 2;   // 0..28 (A k offset, float4)
  const int bkr = tid >> 5;        // 0..7  (B k row group)
  const int bnc = (tid & 31) << 2; // 0..124 (B n offset, float4)

  for (int k0 = 0; k0 < Dd; k0 += BK) {
    // ---- load A tile [BM x BK], convert to tf32 (rna) on the way in ----
#pragma unroll
    for (int i = 0; i < 4; i++) {
      int r = ar + i * 32;
      float4 v = *reinterpret_cast<const float4*>(A + (size_t)(m0 + r) * Dd + k0 + ac);
      float4 w;
      w.x = to_tf32(v.x); w.y = to_tf32(v.y); w.z = to_tf32(v.z); w.w = to_tf32(v.w);
      *reinterpret_cast<float4*>(&As[r][ac]) = w;
    }
    // ---- load B tile [BK x BN] ----
#pragma unroll
    for (int i = 0; i < 4; i++) {
      int kk = bkr + i * 8;
      float4 v = *reinterpret_cast<const float4*>(W + (size_t)(k0 + kk) * Dd + n0 + bnc);
      float4 w;
      w.x = to_tf32(v.x); w.y = to_tf32(v.y); w.z = to_tf32(v.z); w.w = to_tf32(v.w);
      *reinterpret_cast<float4*>(&Bs[kk][bnc]) = w;
    }
    __syncthreads();

#pragma unroll
    for (int ks = 0; ks < BK; ks += 8) {
      uint32_t af[4][4], bf[4][2];
#pragma unroll
      for (int mi = 0; mi < 4; mi++) {
        int mr = warp_m + mi * 16 + g;
        af[mi][0] = __float_as_uint(As[mr][ks + t]);
        af[mi][1] = __float_as_uint(As[mr + 8][ks + t]);
        af[mi][2] = __float_as_uint(As[mr][ks + t + 4]);
        af[mi][3] = __float_as_uint(As[mr + 8][ks + t + 4]);
      }
#pragma unroll
      for (int ni = 0; ni < 4; ni++) {
        int nc = warp_n + ni * 8 + g;
        bf[ni][0] = __float_as_uint(Bs[ks + t][nc]);
        bf[ni][1] = __float_as_uint(Bs[ks + t + 4][nc]);
      }
#pragma unroll
      for (int mi = 0; mi < 4; mi++)
#pragma unroll
        for (int ni = 0; ni < 4; ni++)
          mma_tf32(acc[mi][ni], af[mi][0], af[mi][1], af[mi][2], af[mi][3],
                   bf[ni][0], bf[ni][1]);
    }
    __syncthreads();
  }

  // ---- epilogue: bias add + store ----
#pragma unroll
  for (int mi = 0; mi < 4; mi++) {
    int r0 = m0 + warp_m + mi * 16 + g;
#pragma unroll
    for (int ni = 0; ni < 4; ni++) {
      int c = n0 + warp_n + ni * 8 + 2 * t;
      float b0v = bias[c], b1v = bias[c + 1];
      float2 v0 = make_float2(acc[mi][ni][0] + b0v, acc[mi][ni][1] + b1v);
      float2 v1 = make_float2(acc[mi][ni][2] + b0v, acc[mi][ni][3] + b1v);
      *reinterpret_cast<float2*>(Out + (size_t)r0 * Dd + c) = v0;
      *reinterpret_cast<float2*>(Out + (size_t)(r0 + 8) * Dd + c) = v1;
    }
  }
}

// One CTA per batch; warp h handles head h. Exact fp32 attention.
__global__ __launch_bounds__(256) void attn_kernel(const float* __restrict__ pb) {
  __shared__ float sQ[Ss * Dd], sK[Ss * Dd], sV[Ss * Dd];
  __shared__ float sA[Hh][Ss][Ss];
  const int b = blockIdx.x;
  const int tid = threadIdx.x;
  const size_t base = (size_t)b * (Ss * Dd);

  for (int i = tid; i < Ss * Dd; i += 256) {
    sQ[i] = g_Q[base + i];
    sK[i] = g_K[base + i];
    sV[i] = g_V[base + i];
  }
  __syncthreads();

  const int h = tid >> 5, lane = tid & 31;
  const int c0 = h * HDd;

  if (lane < Ss * Ss) {
    int s = lane / Ss, tt = lane % Ss;
    float acc = 0.f;
#pragma unroll
    for (int d = 0; d < HDd; d++)
      acc += sQ[s * Dd + c0 + d] * sK[tt * Dd + c0 + d];
    sA[h][s][tt] = acc * 0.125f + pb[(h * Ss + s) * Ss + tt];
  }
  __syncwarp();

  if (lane < Ss) {
    float m = sA[h][lane][0];
#pragma unroll
    for (int tt = 1; tt < Ss; tt++) m = fmaxf(m, sA[h][lane][tt]);
    float e[Ss];
    float sum = 0.f;
#pragma unroll
    for (int tt = 0; tt < Ss; tt++) {
      e[tt] = expf(sA[h][lane][tt] - m);
      sum += e[tt];
    }
    float inv = 1.0f / sum;
#pragma unroll
    for (int tt = 0; tt < Ss; tt++) sA[h][lane][tt] = e[tt] * inv;
  }
  __syncwarp();

#pragma unroll
  for (int s = 0; s < Ss; s++) {
    float o0 = 0.f, o1 = 0.f;
#pragma unroll
    for (int tt = 0; tt < Ss; tt++) {
      float a = sA[h][s][tt];
      o0 += a * sV[tt * Dd + c0 + lane];
      o1 += a * sV[tt * Dd + c0 + lane + 32];
    }
    g_O[base + s * Dd + c0 + lane] = o0;
    g_O[base + s * Dd + c0 + lane + 32] = o1;
  }
}

extern "C" void kernel_launch(void* const* d_in, const int* in_sizes, int n_in,
                              void* d_out, int out_size) {
  (void)in_sizes; (void)n_in; (void)out_size;
  const float* x  = (const float*)d_in[0];
  const float* Wq = (const float*)d_in[1];
  const float* bq = (const float*)d_in[2];
  const float* Wk = (const float*)d_in[3];
  const float* bk = (const float*)d_in[4];
  const float* Wv = (const float*)d_in[5];
  const float* bv = (const float*)d_in[6];
  const float* Wo = (const float*)d_in[7];
  const float* bo = (const float*)d_in[8];
  const float* pb = (const float*)d_in[9];
  float* out = (float*)d_out;

  void *qp = nullptr, *kp = nullptr, *vp = nullptr, *op = nullptr;
  cudaGetSymbolAddress(&qp, g_Q);
  cudaGetSymbolAddress(&kp, g_K);
  cudaGetSymbolAddress(&vp, g_V);
  cudaGetSymbolAddress(&op, g_O);

  // 1) QKV projection: [81920,512] x [512, 3*512]
  dim3 grid1(12, Mm / BM);
  gemm_tf32_kernel<<<grid1, 256>>>(x, Wq, Wk, Wv, bq, bk, bv,
                                   (float*)qp, (float*)kp, (float*)vp);
  // 2) attention per batch
  attn_kernel<<<Bb, 256>>>(pb);
  // 3) output projection: [81920,512] x [512,512]
  dim3 grid3(4, Mm / BM);
  gemm_tf32_kernel<<<grid3, 256>>>((const float*)op, Wo, Wo, Wo, bo, bo, bo,
                                   out, out, out);
}